// round 7
// baseline (speedup 1.0000x reference)
#include <cuda_runtime.h>
#include <cstdint>
#include <cstddef>

#define T_STEPS 256
#define BATCH   64
#define DIN     512
#define R       2048
#define DOUT    128
#define NW      (R*R)            // 4194304
#define KEEPK   838860u          // max(1, int(NW * (1-0.8)))
#define BETA    0.9f
#define KS      16               // K-split for step GEMM
#define KSL     (R/KS)           // 128

// ---------------- device scratch (static, no allocation) ----------------
__device__ float      g_weff [NW];                                  // 16 MB
__device__ float      g_drive[(size_t)T_STEPS*BATCH*R];             // 128 MB
__device__ float      g_part [(size_t)KS*BATCH*R];                  // 8 MB
__device__ float      g_V    [BATCH*R];
__device__ float      g_St   [R*BATCH];                             // spikes transposed [i][b]
__device__ unsigned   g_bits [(size_t)T_STEPS*BATCH*(R/32)];        // 4 MB spike bitmasks
__device__ unsigned   g_hist1[65536];
__device__ unsigned   g_hist2[65536];
__device__ unsigned   g_bucket;
__device__ unsigned   g_krem;
__device__ unsigned   g_cntabove;
__device__ float      g_thresh;
__device__ float      g_active_ratio;
__device__ unsigned long long g_spk;

// ---------------- packed fp32x2 helpers (sm_103a FFMA2 path) ----------------
__device__ __forceinline__ void ffma2(unsigned long long& d,
                                      unsigned long long a,
                                      unsigned long long b) {
    asm("fma.rn.f32x2 %0, %1, %2, %0;" : "+l"(d) : "l"(a), "l"(b));
}
__device__ __forceinline__ unsigned long long pk2(float v) {
    unsigned long long r;
    asm("mov.b64 %0, {%1, %1};" : "=l"(r) : "f"(v));
    return r;
}

// ---------------- threshold selection (exact, 2-pass radix) ----------------
__global__ void hist1_k(const float* __restrict__ w) {
    unsigned i = blockIdx.x * blockDim.x + threadIdx.x;
    unsigned stride = gridDim.x * blockDim.x;
    for (; i < NW; i += stride) {
        unsigned key = __float_as_uint(w[i]) & 0x7fffffffu;
        atomicAdd(&g_hist1[key >> 16], 1u);
    }
}

__global__ void sel1_k() {
    __shared__ unsigned ssum[1024];
    int t = threadIdx.x;
    unsigned s = 0;
    for (int j = 0; j < 64; j++) s += g_hist1[t*64 + j];
    ssum[t] = s;
    __syncthreads();
    if (t == 0) {
        unsigned long long cum = 0;
        int c = 1023;
        for (; c >= 0; c--) {
            if (cum + ssum[c] >= (unsigned long long)KEEPK) break;
            cum += ssum[c];
        }
        unsigned bucket = 0;
        for (int j = 63; j >= 0; j--) {
            unsigned h = g_hist1[c*64 + j];
            if (cum + h >= (unsigned long long)KEEPK) { bucket = (unsigned)(c*64 + j); break; }
            cum += h;
        }
        g_bucket   = bucket;
        g_cntabove = (unsigned)cum;            // count with top16 strictly above bucket
        g_krem     = KEEPK - (unsigned)cum;    // rank remaining inside bucket
    }
}

__global__ void hist2_k(const float* __restrict__ w) {
    unsigned bucket = g_bucket;
    unsigned i = blockIdx.x * blockDim.x + threadIdx.x;
    unsigned stride = gridDim.x * blockDim.x;
    for (; i < NW; i += stride) {
        unsigned key = __float_as_uint(w[i]) & 0x7fffffffu;
        if ((key >> 16) == bucket) atomicAdd(&g_hist2[key & 0xffffu], 1u);
    }
}

__global__ void sel2_k() {
    __shared__ unsigned ssum[1024];
    int t = threadIdx.x;
    unsigned s = 0;
    for (int j = 0; j < 64; j++) s += g_hist2[t*64 + j];
    ssum[t] = s;
    __syncthreads();
    if (t == 0) {
        unsigned krem = g_krem;
        unsigned long long cum = 0;
        int c = 1023;
        for (; c >= 0; c--) {
            if (cum + ssum[c] >= (unsigned long long)krem) break;
            cum += ssum[c];
        }
        unsigned low = 0;
        for (int j = 63; j >= 0; j--) {
            unsigned h = g_hist2[c*64 + j];
            cum += h;
            if (cum >= (unsigned long long)krem) { low = (unsigned)(c*64 + j); break; }
        }
        unsigned bits = (g_bucket << 16) | low;
        g_thresh = __uint_as_float(bits);
        unsigned long long cnt_ge = (unsigned long long)g_cntabove + cum;
        g_active_ratio = (float)((double)cnt_ge / (double)NW);
    }
}

__global__ void weff_k(const float* __restrict__ w) {
    float th = g_thresh;
    unsigned i = blockIdx.x * blockDim.x + threadIdx.x;
    if (i < NW) {
        float v = w[i];
        g_weff[i] = (fabsf(v) >= th) ? v : 0.0f;
    }
}

// ---------------- input projection: drive = x @ w_in + b_in ----------------
// C[M=16384][N=2048], K=512. 64x64 tile, 256 threads, 4x4 per thread (FFMA2).
#define BM 64
#define BN 64
#define BK 16
__global__ void __launch_bounds__(256) drive_k(const float* __restrict__ A,
                                               const float* __restrict__ Bw,
                                               const float* __restrict__ bias) {
    __shared__ __align__(16) float sA[BK][BM];
    __shared__ __align__(16) float sB[BK][BN];
    int bm = blockIdx.y * BM;
    int bn = blockIdx.x * BN;
    int tid = threadIdx.x;
    int tx = tid & 15, ty = tid >> 4;
    unsigned long long acc[4][2];
    #pragma unroll
    for (int i = 0; i < 4; i++) { acc[i][0] = 0ull; acc[i][1] = 0ull; }

    for (int k0 = 0; k0 < DIN; k0 += BK) {
        #pragma unroll
        for (int e = 0; e < 4; e++) {
            int idx = tid + e * 256;
            int m = idx >> 4, k = idx & 15;
            sA[k][m] = A[(size_t)(bm + m) * DIN + k0 + k];
        }
        #pragma unroll
        for (int e = 0; e < 4; e++) {
            int idx = tid + e * 256;
            int k = idx >> 6, n = idx & 63;
            sB[k][n] = Bw[(size_t)(k0 + k) * R + bn + n];
        }
        __syncthreads();
        #pragma unroll
        for (int k = 0; k < BK; k++) {
            float4 av = *reinterpret_cast<const float4*>(&sA[k][ty*4]);
            ulonglong2 bv = *reinterpret_cast<const ulonglong2*>(&sB[k][tx*4]);
            unsigned long long a0 = pk2(av.x), a1 = pk2(av.y), a2 = pk2(av.z), a3 = pk2(av.w);
            ffma2(acc[0][0], a0, bv.x); ffma2(acc[0][1], a0, bv.y);
            ffma2(acc[1][0], a1, bv.x); ffma2(acc[1][1], a1, bv.y);
            ffma2(acc[2][0], a2, bv.x); ffma2(acc[2][1], a2, bv.y);
            ffma2(acc[3][0], a3, bv.x); ffma2(acc[3][1], a3, bv.y);
        }
        __syncthreads();
    }
    float b0 = bias[bn + tx*4 + 0], b1 = bias[bn + tx*4 + 1];
    float b2 = bias[bn + tx*4 + 2], b3 = bias[bn + tx*4 + 3];
    #pragma unroll
    for (int i = 0; i < 4; i++) {
        float2 lo = reinterpret_cast<float2&>(acc[i][0]);
        float2 hi = reinterpret_cast<float2&>(acc[i][1]);
        float4 outv = make_float4(lo.x + b0, lo.y + b1, hi.x + b2, hi.y + b3);
        *reinterpret_cast<float4*>(
            &g_drive[(size_t)(bm + ty*4 + i) * R + bn + tx*4]) = outv;
    }
}

// ---------------- recurrent step: phase A  (partial = s_prev @ W_eff, K-split) ----------------
// grid (4 jtiles, 4 bgroups, KS), 128 threads; thread owns 4 j cols x 16 batches.
// FFMA2: spikes pre-packed {s,s}; per i-row: 32 FFMA2 + 8 LDS.128 + 1 LDG.128.
__global__ void __launch_bounds__(128) stepA_k() {
    __shared__ __align__(16) unsigned long long ssh2[KSL][16];   // 16 KB: {s,s} per (i,b)
    int jt = blockIdx.x, bg = blockIdx.y, ks = blockIdx.z;
    int tid = threadIdx.x;
    int j0 = jt * 512 + tid * 4;
    int i0 = ks * KSL;

    for (int e = tid; e < KSL * 16; e += 128) {
        int i = e >> 4, bb = e & 15;
        unsigned u = __float_as_uint(g_St[(size_t)(i0 + i) * BATCH + bg * 16 + bb]);
        ssh2[i][bb] = ((unsigned long long)u << 32) | (unsigned long long)u;
    }
    __syncthreads();

    unsigned long long acc[16][2];
    #pragma unroll
    for (int bb = 0; bb < 16; bb++) { acc[bb][0] = 0ull; acc[bb][1] = 0ull; }

    const float* wrow = &g_weff[(size_t)i0 * R + j0];
    #pragma unroll 4
    for (int i = 0; i < KSL; i++) {
        ulonglong2 w = *reinterpret_cast<const ulonglong2*>(wrow);   // {w0,w1},{w2,w3}
        wrow += R;
        const ulonglong2* sp = reinterpret_cast<const ulonglong2*>(&ssh2[i][0]);
        ulonglong2 p0 = sp[0], p1 = sp[1], p2 = sp[2], p3 = sp[3];
        ulonglong2 p4 = sp[4], p5 = sp[5], p6 = sp[6], p7 = sp[7];
        ffma2(acc[0][0],  p0.x, w.x); ffma2(acc[0][1],  p0.x, w.y);
        ffma2(acc[1][0],  p0.y, w.x); ffma2(acc[1][1],  p0.y, w.y);
        ffma2(acc[2][0],  p1.x, w.x); ffma2(acc[2][1],  p1.x, w.y);
        ffma2(acc[3][0],  p1.y, w.x); ffma2(acc[3][1],  p1.y, w.y);
        ffma2(acc[4][0],  p2.x, w.x); ffma2(acc[4][1],  p2.x, w.y);
        ffma2(acc[5][0],  p2.y, w.x); ffma2(acc[5][1],  p2.y, w.y);
        ffma2(acc[6][0],  p3.x, w.x); ffma2(acc[6][1],  p3.x, w.y);
        ffma2(acc[7][0],  p3.y, w.x); ffma2(acc[7][1],  p3.y, w.y);
        ffma2(acc[8][0],  p4.x, w.x); ffma2(acc[8][1],  p4.x, w.y);
        ffma2(acc[9][0],  p4.y, w.x); ffma2(acc[9][1],  p4.y, w.y);
        ffma2(acc[10][0], p5.x, w.x); ffma2(acc[10][1], p5.x, w.y);
        ffma2(acc[11][0], p5.y, w.x); ffma2(acc[11][1], p5.y, w.y);
        ffma2(acc[12][0], p6.x, w.x); ffma2(acc[12][1], p6.x, w.y);
        ffma2(acc[13][0], p6.y, w.x); ffma2(acc[13][1], p6.y, w.y);
        ffma2(acc[14][0], p7.x, w.x); ffma2(acc[14][1], p7.x, w.y);
        ffma2(acc[15][0], p7.y, w.x); ffma2(acc[15][1], p7.y, w.y);
    }
    #pragma unroll
    for (int bb = 0; bb < 16; bb++) {
        ulonglong2 outv; outv.x = acc[bb][0]; outv.y = acc[bb][1];
        *reinterpret_cast<ulonglong2*>(
            &g_part[((size_t)ks * BATCH + bg * 16 + bb) * R + j0]) = outv;
    }
}

// ---------------- recurrent step: phase B  (reduce + LIF + spike) ----------------
__global__ void __launch_bounds__(256) stepB_k(int t) {
    int idx = blockIdx.x * 256 + threadIdx.x;     // 0..131071
    int b = idx >> 11;
    int j = idx & (R - 1);

    float sum = g_drive[((size_t)t * BATCH + b) * R + j];
    #pragma unroll
    for (int ks = 0; ks < KS; ks++)
        sum += g_part[((size_t)ks * BATCH + b) * R + j];

    float V = BETA * g_V[idx] + sum;
    float s = (V > 1.0f) ? 1.0f : 0.0f;
    V -= s;
    g_V[idx] = V;
    g_St[(size_t)j * BATCH + b] = s;

    unsigned ballot = __ballot_sync(0xffffffffu, s != 0.0f);
    __shared__ int ssum;
    if (threadIdx.x == 0) ssum = 0;
    __syncthreads();
    if ((threadIdx.x & 31) == 0) {
        g_bits[((size_t)t * BATCH + b) * (R / 32) + (j >> 5)] = ballot;
        atomicAdd(&ssum, __popc(ballot));
    }
    __syncthreads();
    if (threadIdx.x == 0) atomicAdd(&g_spk, (unsigned long long)ssum);
}

// ---------------- logits for all (t,b) from spike bitmasks ----------------
__global__ void __launch_bounds__(128) logits_k(const float* __restrict__ wh,
                                                const float* __restrict__ bh,
                                                float* __restrict__ out) {
    int tb = blockIdx.x;      // t*64 + b
    int d = threadIdx.x;
    __shared__ unsigned bits[64];
    if (d < 64) bits[d] = g_bits[(size_t)tb * 64 + d];
    __syncthreads();
    float acc = bh[d];
    #pragma unroll 1
    for (int w = 0; w < 64; w++) {
        unsigned m = bits[w];
        while (m) {                 // uniform across warp (m from shared)
            int k = __ffs(m) - 1;
            m &= m - 1;
            acc += wh[(size_t)(w * 32 + k) * DOUT + d];
        }
    }
    out[(size_t)tb * DOUT + d] = acc;
}

// ---------------- readout = mean over T ----------------
__global__ void readout_k(const float* __restrict__ logits, float* __restrict__ out) {
    int idx = blockIdx.x * 256 + threadIdx.x;   // 0..8191
    if (idx < BATCH * DOUT) {
        float s = 0.f;
        for (int t = 0; t < T_STEPS; t++) s += logits[(size_t)t * BATCH * DOUT + idx];
        out[idx] = s * (1.0f / T_STEPS);
    }
}

__global__ void scalars_k(float* __restrict__ out) {
    out[0] = (float)((double)g_spk / (double)((size_t)T_STEPS * BATCH * R)); // spike_rate
    out[1] = g_active_ratio;                                                 // active_ratio
}

// ---------------- launch ----------------
extern "C" void kernel_launch(void* const* d_in, const int* in_sizes, int n_in,
                              void* d_out, int out_size) {
    const float* x      = (const float*)d_in[0];
    const float* w_in   = (const float*)d_in[1];
    const float* b_in   = (const float*)d_in[2];
    const float* w_rec  = (const float*)d_in[3];
    const float* w_head = (const float*)d_in[4];
    const float* b_head = (const float*)d_in[5];
    float* out = (float*)d_out;

    void *h1p, *h2p, *vp, *stp, *spkp;
    cudaGetSymbolAddress(&h1p,  g_hist1);
    cudaGetSymbolAddress(&h2p,  g_hist2);
    cudaGetSymbolAddress(&vp,   g_V);
    cudaGetSymbolAddress(&stp,  g_St);
    cudaGetSymbolAddress(&spkp, g_spk);

    cudaMemsetAsync(h1p,  0, 65536 * sizeof(unsigned));
    cudaMemsetAsync(h2p,  0, 65536 * sizeof(unsigned));
    cudaMemsetAsync(vp,   0, BATCH * R * sizeof(float));
    cudaMemsetAsync(stp,  0, R * BATCH * sizeof(float));
    cudaMemsetAsync(spkp, 0, sizeof(unsigned long long));

    // exact top-k threshold
    hist1_k<<<2048, 512>>>(w_rec);
    sel1_k<<<1, 1024>>>();
    hist2_k<<<2048, 512>>>(w_rec);
    sel2_k<<<1, 1024>>>();
    weff_k<<<NW / 256, 256>>>(w_rec);

    // input projection
    drive_k<<<dim3(R / BN, (T_STEPS * BATCH) / BM), 256>>>(x, w_in, b_in);

    // sequential LIF scan
    for (int t = 0; t < T_STEPS; t++) {
        stepA_k<<<dim3(4, 4, KS), 128>>>();
        stepB_k<<<(BATCH * R) / 256, 256>>>(t);
    }

    // outputs: [readout 8192][logits_seq 2097152][spike_rate 1][active_ratio 1]
    float* logits_out = out + BATCH * DOUT;
    logits_k<<<T_STEPS * BATCH, 128>>>(w_head, b_head, logits_out);
    readout_k<<<(BATCH * DOUT + 255) / 256, 256>>>(logits_out, out);
    scalars_k<<<1, 1>>>(out + BATCH * DOUT + (size_t)T_STEPS * BATCH * DOUT);
}

// round 11
// speedup vs baseline: 1.4111x; 1.4111x over previous
#include <cuda_runtime.h>
#include <cstdint>
#include <cstddef>

#define T_STEPS 256
#define BATCH   64
#define DIN     512
#define R       2048
#define DOUT    128
#define NW      (R*R)            // 4194304
#define KEEPK   838860u          // max(1, int(NW * (1-0.8)))
#define BETA    0.9f
#define NCH     16               // row chunks — MUST match round-0 KS for bitwise identity
#define CHR     (R/NCH)          // 128 rows per chunk
#define MAXNZ   64               // capacity per (chunk, col); mean 25.6, 8.5 sigma safe
#define SSTRIDE 20               // padded u16 row stride (40B) -> conflict-free LDS.64

// ---------------- device scratch (static, no allocation) ----------------
__device__ float      g_drive[(size_t)T_STEPS*BATCH*R];             // 128 MB
__device__ float      g_part [(size_t)NCH*BATCH*R];                 // 8 MB
__device__ float      g_V    [BATCH*R];
__device__ unsigned short g_St16[R*BATCH];                          // spikes as f32-high-half u16, [i][b]
__device__ uint2      g_ent  [(size_t)NCH*MAXNZ*R];                 // {w_bits, row} 16 MB
__device__ int        g_cnt  [NCH*R];
__device__ unsigned   g_bits [(size_t)T_STEPS*BATCH*(R/32)];        // 4 MB spike bitmasks
__device__ unsigned   g_hist1[65536];
__device__ unsigned   g_hist2[65536];
__device__ unsigned   g_bucket;
__device__ unsigned   g_krem;
__device__ unsigned   g_cntabove;
__device__ float      g_thresh;
__device__ float      g_active_ratio;
__device__ unsigned long long g_spk;

// ---------------- threshold selection (exact, 2-pass radix) ----------------
__global__ void hist1_k(const float* __restrict__ w) {
    unsigned i = blockIdx.x * blockDim.x + threadIdx.x;
    unsigned stride = gridDim.x * blockDim.x;
    for (; i < NW; i += stride) {
        unsigned key = __float_as_uint(w[i]) & 0x7fffffffu;
        atomicAdd(&g_hist1[key >> 16], 1u);
    }
}

__global__ void sel1_k() {
    __shared__ unsigned ssum[1024];
    int t = threadIdx.x;
    unsigned s = 0;
    for (int j = 0; j < 64; j++) s += g_hist1[t*64 + j];
    ssum[t] = s;
    __syncthreads();
    if (t == 0) {
        unsigned long long cum = 0;
        int c = 1023;
        for (; c >= 0; c--) {
            if (cum + ssum[c] >= (unsigned long long)KEEPK) break;
            cum += ssum[c];
        }
        unsigned bucket = 0;
        for (int j = 63; j >= 0; j--) {
            unsigned h = g_hist1[c*64 + j];
            if (cum + h >= (unsigned long long)KEEPK) { bucket = (unsigned)(c*64 + j); break; }
            cum += h;
        }
        g_bucket   = bucket;
        g_cntabove = (unsigned)cum;
        g_krem     = KEEPK - (unsigned)cum;
    }
}

__global__ void hist2_k(const float* __restrict__ w) {
    unsigned bucket = g_bucket;
    unsigned i = blockIdx.x * blockDim.x + threadIdx.x;
    unsigned stride = gridDim.x * blockDim.x;
    for (; i < NW; i += stride) {
        unsigned key = __float_as_uint(w[i]) & 0x7fffffffu;
        if ((key >> 16) == bucket) atomicAdd(&g_hist2[key & 0xffffu], 1u);
    }
}

__global__ void sel2_k() {
    __shared__ unsigned ssum[1024];
    int t = threadIdx.x;
    unsigned s = 0;
    for (int j = 0; j < 64; j++) s += g_hist2[t*64 + j];
    ssum[t] = s;
    __syncthreads();
    if (t == 0) {
        unsigned krem = g_krem;
        unsigned long long cum = 0;
        int c = 1023;
        for (; c >= 0; c--) {
            if (cum + ssum[c] >= (unsigned long long)krem) break;
            cum += ssum[c];
        }
        unsigned low = 0;
        for (int j = 63; j >= 0; j--) {
            unsigned h = g_hist2[c*64 + j];
            cum += h;
            if (cum >= (unsigned long long)krem) { low = (unsigned)(c*64 + j); break; }
        }
        unsigned bits = (g_bucket << 16) | low;
        g_thresh = __uint_as_float(bits);
        unsigned long long cnt_ge = (unsigned long long)g_cntabove + cum;
        g_active_ratio = (float)((double)cnt_ge / (double)NW);
    }
}

// ---------------- build padded column-compressed W_eff ----------------
// thread = (chunk, col); scans its 128 rows in ascending order (deterministic,
// matching the dense round-0 accumulation order exactly).
__global__ void __launch_bounds__(128) build_k(const float* __restrict__ w) {
    int idx = blockIdx.x * 128 + threadIdx.x;       // 0 .. NCH*R-1
    if (idx >= NCH * R) return;
    int chunk = idx >> 11;
    int col   = idx & (R - 1);
    float th = g_thresh;
    int cnt = 0;
    #pragma unroll 4
    for (int r = 0; r < CHR; r++) {
        float v = w[(size_t)(chunk * CHR + r) * R + col];
        if (fabsf(v) >= th && cnt < MAXNZ) {
            g_ent[((size_t)chunk * MAXNZ + cnt) * R + col] =
                make_uint2(__float_as_uint(v), (unsigned)r);
            cnt++;
        }
    }
    g_cnt[idx] = cnt;
}

// ---------------- input projection: drive = x @ w_in + b_in (round-0 fp32) ----------------
#define BM 64
#define BN 64
#define BK 16
__global__ void __launch_bounds__(256) drive_k(const float* __restrict__ A,
                                               const float* __restrict__ Bw,
                                               const float* __restrict__ bias) {
    __shared__ float sA[BK][BM + 1];
    __shared__ float sB[BK][BN + 1];
    int bm = blockIdx.y * BM;
    int bn = blockIdx.x * BN;
    int tid = threadIdx.x;
    int tx = tid & 15, ty = tid >> 4;
    float acc[4][4] = {};
    for (int k0 = 0; k0 < DIN; k0 += BK) {
        #pragma unroll
        for (int e = 0; e < 4; e++) {
            int idx = tid + e * 256;
            int m = idx >> 4, k = idx & 15;
            sA[k][m] = A[(size_t)(bm + m) * DIN + k0 + k];
        }
        #pragma unroll
        for (int e = 0; e < 4; e++) {
            int idx = tid + e * 256;
            int k = idx >> 6, n = idx & 63;
            sB[k][n] = Bw[(size_t)(k0 + k) * R + bn + n];
        }
        __syncthreads();
        #pragma unroll
        for (int k = 0; k < BK; k++) {
            float a[4], b[4];
            #pragma unroll
            for (int u = 0; u < 4; u++) a[u] = sA[k][ty*4 + u];
            #pragma unroll
            for (int u = 0; u < 4; u++) b[u] = sB[k][tx*4 + u];
            #pragma unroll
            for (int i = 0; i < 4; i++)
                #pragma unroll
                for (int j = 0; j < 4; j++)
                    acc[i][j] += a[i] * b[j];
        }
        __syncthreads();
    }
    #pragma unroll
    for (int i = 0; i < 4; i++)
        #pragma unroll
        for (int j = 0; j < 4; j++)
            g_drive[(size_t)(bm + ty*4 + i) * R + bn + tx*4 + j] = acc[i][j] + bias[bn + tx*4 + j];
}

// ---------------- recurrent step phase A: SPARSE partial = s_prev @ W_eff ----------------
// grid (16 coltiles, 4 bgroups, NCH chunks), 128 threads.
// Thread owns 1 column x 16 batches. Per (col,batch): FFMA chain over nonzeros
// in ascending row order == dense chain with exact-zero terms elided (bitwise
// identical to the round-0 dense kernel).
__global__ void __launch_bounds__(128) stepS_k() {
    __shared__ __align__(8) unsigned short ssh[CHR * SSTRIDE];    // 5 KB
    int tid = threadIdx.x;
    int col   = blockIdx.x * 128 + tid;
    int bg    = blockIdx.y;
    int chunk = blockIdx.z;
    int i0 = chunk * CHR;

    // fill spike tile: 128 rows x 16 batches, 4 u16 (8B) per transaction
    for (int e2 = tid; e2 < CHR * 4; e2 += 128) {
        int i = e2 >> 2, q = e2 & 3;
        *reinterpret_cast<uint2*>(&ssh[i * SSTRIDE + q * 4]) =
            *reinterpret_cast<const uint2*>(&g_St16[(size_t)(i0 + i) * BATCH + bg * 16 + q * 4]);
    }
    __syncthreads();

    float acc[16];
    #pragma unroll
    for (int bb = 0; bb < 16; bb++) acc[bb] = 0.0f;

    int cnt = g_cnt[chunk * R + col];
    const uint2* p = &g_ent[(size_t)chunk * MAXNZ * R + col];

    #pragma unroll 2
    for (int rank = 0; rank < cnt; rank++) {
        uint2 e = p[(size_t)rank * R];
        float w = __uint_as_float(e.x);
        int r = (int)e.y;
        const unsigned short* row = &ssh[r * SSTRIDE];
        uint2 q0 = *reinterpret_cast<const uint2*>(row + 0);
        uint2 q1 = *reinterpret_cast<const uint2*>(row + 4);
        uint2 q2 = *reinterpret_cast<const uint2*>(row + 8);
        uint2 q3 = *reinterpret_cast<const uint2*>(row + 12);
        // each u32 holds two u16 spike values (= f32 high halves); expansion exact for 0/1
        acc[0]  += w * __uint_as_float(q0.x << 16);
        acc[1]  += w * __uint_as_float(q0.x & 0xffff0000u);
        acc[2]  += w * __uint_as_float(q0.y << 16);
        acc[3]  += w * __uint_as_float(q0.y & 0xffff0000u);
        acc[4]  += w * __uint_as_float(q1.x << 16);
        acc[5]  += w * __uint_as_float(q1.x & 0xffff0000u);
        acc[6]  += w * __uint_as_float(q1.y << 16);
        acc[7]  += w * __uint_as_float(q1.y & 0xffff0000u);
        acc[8]  += w * __uint_as_float(q2.x << 16);
        acc[9]  += w * __uint_as_float(q2.x & 0xffff0000u);
        acc[10] += w * __uint_as_float(q2.y << 16);
        acc[11] += w * __uint_as_float(q2.y & 0xffff0000u);
        acc[12] += w * __uint_as_float(q3.x << 16);
        acc[13] += w * __uint_as_float(q3.x & 0xffff0000u);
        acc[14] += w * __uint_as_float(q3.y << 16);
        acc[15] += w * __uint_as_float(q3.y & 0xffff0000u);
    }

    #pragma unroll
    for (int bb = 0; bb < 16; bb++)
        g_part[((size_t)chunk * BATCH + bg * 16 + bb) * R + col] = acc[bb];
}

// ---------------- recurrent step phase B: reduce + LIF + spike ----------------
// identical partial-sum order to round-0 (16 chunks, ascending)
__global__ void __launch_bounds__(256) stepB_k(int t) {
    int idx = blockIdx.x * 256 + threadIdx.x;     // 0..131071
    int b = idx >> 11;
    int j = idx & (R - 1);

    float sum = g_drive[((size_t)t * BATCH + b) * R + j];
    #pragma unroll
    for (int ks = 0; ks < NCH; ks++)
        sum += g_part[((size_t)ks * BATCH + b) * R + j];

    float V = BETA * g_V[idx] + sum;
    float s = (V > 1.0f) ? 1.0f : 0.0f;
    V -= s;
    g_V[idx] = V;
    g_St16[(size_t)j * BATCH + b] = (s != 0.0f) ? (unsigned short)0x3F80 : (unsigned short)0;

    unsigned ballot = __ballot_sync(0xffffffffu, s != 0.0f);
    __shared__ int ssum;
    if (threadIdx.x == 0) ssum = 0;
    __syncthreads();
    if ((threadIdx.x & 31) == 0) {
        g_bits[((size_t)t * BATCH + b) * (R / 32) + (j >> 5)] = ballot;
        atomicAdd(&ssum, __popc(ballot));
    }
    __syncthreads();
    if (threadIdx.x == 0) atomicAdd(&g_spk, (unsigned long long)ssum);
}

// ---------------- logits for all (t,b) from spike bitmasks ----------------
__global__ void __launch_bounds__(128) logits_k(const float* __restrict__ wh,
                                                const float* __restrict__ bh,
                                                float* __restrict__ out) {
    int tb = blockIdx.x;      // t*64 + b
    int d = threadIdx.x;
    __shared__ unsigned bits[64];
    if (d < 64) bits[d] = g_bits[(size_t)tb * 64 + d];
    __syncthreads();
    float acc = bh[d];
    #pragma unroll 1
    for (int w = 0; w < 64; w++) {
        unsigned m = bits[w];
        while (m) {                 // uniform across warp (m from shared)
            int k = __ffs(m) - 1;
            m &= m - 1;
            acc += wh[(size_t)(w * 32 + k) * DOUT + d];
        }
    }
    out[(size_t)tb * DOUT + d] = acc;
}

// ---------------- readout = mean over T ----------------
__global__ void readout_k(const float* __restrict__ logits, float* __restrict__ out) {
    int idx = blockIdx.x * 256 + threadIdx.x;   // 0..8191
    if (idx < BATCH * DOUT) {
        float s = 0.f;
        for (int t = 0; t < T_STEPS; t++) s += logits[(size_t)t * BATCH * DOUT + idx];
        out[idx] = s * (1.0f / T_STEPS);
    }
}

__global__ void scalars_k(float* __restrict__ out) {
    out[0] = (float)((double)g_spk / (double)((size_t)T_STEPS * BATCH * R)); // spike_rate
    out[1] = g_active_ratio;                                                 // active_ratio
}

// ---------------- launch ----------------
extern "C" void kernel_launch(void* const* d_in, const int* in_sizes, int n_in,
                              void* d_out, int out_size) {
    const float* x      = (const float*)d_in[0];
    const float* w_in   = (const float*)d_in[1];
    const float* b_in   = (const float*)d_in[2];
    const float* w_rec  = (const float*)d_in[3];
    const float* w_head = (const float*)d_in[4];
    const float* b_head = (const float*)d_in[5];
    float* out = (float*)d_out;

    void *h1p, *h2p, *vp, *stp, *spkp;
    cudaGetSymbolAddress(&h1p,  g_hist1);
    cudaGetSymbolAddress(&h2p,  g_hist2);
    cudaGetSymbolAddress(&vp,   g_V);
    cudaGetSymbolAddress(&stp,  g_St16);
    cudaGetSymbolAddress(&spkp, g_spk);

    cudaMemsetAsync(h1p,  0, 65536 * sizeof(unsigned));
    cudaMemsetAsync(h2p,  0, 65536 * sizeof(unsigned));
    cudaMemsetAsync(vp,   0, BATCH * R * sizeof(float));
    cudaMemsetAsync(stp,  0, R * BATCH * sizeof(unsigned short));
    cudaMemsetAsync(spkp, 0, sizeof(unsigned long long));

    // exact top-k threshold
    hist1_k<<<2048, 512>>>(w_rec);
    sel1_k<<<1, 1024>>>();
    hist2_k<<<2048, 512>>>(w_rec);
    sel2_k<<<1, 1024>>>();

    // build sparse W_eff structure (static across the whole scan)
    build_k<<<(NCH * R) / 128, 128>>>(w_rec);

    // input projection
    drive_k<<<dim3(R / BN, (T_STEPS * BATCH) / BM), 256>>>(x, w_in, b_in);

    // sequential LIF scan (sparse recurrent GEMM, bitwise == dense round-0)
    for (int t = 0; t < T_STEPS; t++) {
        stepS_k<<<dim3(16, 4, NCH), 128>>>();
        stepB_k<<<(BATCH * R) / 256, 256>>>(t);
    }

    // outputs: [readout 8192][logits_seq 2097152][spike_rate 1][active_ratio 1]
    float* logits_out = out + BATCH * DOUT;
    logits_k<<<T_STEPS * BATCH, 128>>>(w_head, b_head, logits_out);
    readout_k<<<(BATCH * DOUT + 255) / 256, 256>>>(logits_out, out);
    scalars_k<<<1, 1>>>(out + BATCH * DOUT + (size_t)T_STEPS * BATCH * DOUT);
}